// round 4
// baseline (speedup 1.0000x reference)
#include <cuda_runtime.h>

#define B 32
#define T 1024
#define D 384
#define T_OUT 4096
#define F4_PER_ROW (D / 4)   // 96

// scratch: frame index per (batch, out_pos); -1 = write zeros
__device__ int g_idx[B * T_OUT];

// ---------------------------------------------------------------------------
// Kernel A: per-batch cumsum + searchsorted -> g_idx
// grid = B, block = 1024 (== T)
// ---------------------------------------------------------------------------
__global__ __launch_bounds__(1024) void build_idx_kernel(
    const int* __restrict__ durations,   // [B, T]
    const int* __restrict__ target_len)  // [B]
{
    __shared__ int s_ends[T + 1];        // +1 sentinel so mid==T is a safe read
    __shared__ int s_warp[32];

    const int b   = blockIdx.x;
    const int tid = threadIdx.x;
    const int lane = tid & 31;
    const int wid  = tid >> 5;

    // load + clamp
    int v = durations[b * T + tid];
    v = v < 0 ? 0 : v;

    // warp inclusive scan
    #pragma unroll
    for (int off = 1; off < 32; off <<= 1) {
        int n = __shfl_up_sync(0xFFFFFFFFu, v, off);
        if (lane >= off) v += n;
    }
    if (lane == 31) s_warp[wid] = v;
    __syncthreads();

    // scan the 32 warp sums (warp 0)
    if (wid == 0) {
        int w = s_warp[lane];
        #pragma unroll
        for (int off = 1; off < 32; off <<= 1) {
            int n = __shfl_up_sync(0xFFFFFFFFu, w, off);
            if (lane >= off) w += n;
        }
        s_warp[lane] = w;
    }
    __syncthreads();

    int add = (wid > 0) ? s_warp[wid - 1] : 0;
    s_ends[tid] = v + add;
    if (tid == 0) s_ends[T] = 0x7FFFFFFF;  // sentinel
    __syncthreads();

    const int total = s_ends[T - 1];
    int tl = target_len[b];
    const int limit = total < tl ? total : tl;

    // each thread handles T_OUT / T = 4 positions
    #pragma unroll
    for (int k = 0; k < T_OUT / T; k++) {
        const int pos = tid + k * T;
        // first index i with ends[i] > pos  (searchsorted side='right')
        // answer space is {0..T} -> 1025 values -> 11 iterations
        int lo = 0, hi = T;
        #pragma unroll
        for (int it = 0; it < 11; it++) {
            int mid = (lo + hi) >> 1;
            if (s_ends[mid] <= pos) lo = mid + 1; else hi = mid;
        }
        int idx = lo < (T - 1) ? lo : (T - 1);
        g_idx[b * T_OUT + pos] = (pos < limit) ? idx : -1;
    }
}

// ---------------------------------------------------------------------------
// Kernel B: gather rows of x (or zeros) into out, float4-vectorized
// Each block of 384 threads handles 4 output rows (96 float4 per row).
// grid = B*T_OUT/4 = 32768
// ---------------------------------------------------------------------------
__global__ __launch_bounds__(384) void gather_kernel(
    const float4* __restrict__ x,   // [B, T, 96] as float4
    float4* __restrict__ out)       // [B, T_OUT, 96] as float4
{
    const int tid  = threadIdx.x;
    const int r    = tid / F4_PER_ROW;        // 0..3
    const int c    = tid - r * F4_PER_ROW;    // 0..95
    const int row  = blockIdx.x * 4 + r;      // global (b, pos) row, < B*T_OUT
    const int b    = row >> 12;               // / T_OUT
    const int pos  = row & (T_OUT - 1);

    const int idx = __ldg(&g_idx[b * T_OUT + pos]);

    float4 val;
    if (idx >= 0) {
        val = __ldg(&x[((long)b * T + idx) * F4_PER_ROW + c]);
    } else {
        val = make_float4(0.f, 0.f, 0.f, 0.f);
    }
    out[(long)row * F4_PER_ROW + c] = val;
}

// ---------------------------------------------------------------------------
extern "C" void kernel_launch(void* const* d_in, const int* in_sizes, int n_in,
                              void* d_out, int out_size)
{
    const float* x          = (const float*)d_in[0];
    const int*   durations  = (const int*)d_in[1];
    const int*   target_len = (const int*)d_in[2];
    float*       out        = (float*)d_out;

    build_idx_kernel<<<B, 1024>>>(durations, target_len);
    gather_kernel<<<(B * T_OUT) / 4, 384>>>((const float4*)x, (float4*)out);
}

// round 7
// speedup vs baseline: 1.3422x; 1.3422x over previous
#include <cuda_runtime.h>

#define B 32
#define T 1024
#define D 384
#define T_OUT 4096
#define F4_PER_ROW (D / 4)        // 96
#define ROWS_PER_THREAD 8
#define ROW_LANES 4               // 384 / 96
#define ROWS_PER_BLOCK (ROW_LANES * ROWS_PER_THREAD)   // 32

// scratch: frame index per (batch, out_pos); -1 = write zeros
__device__ int g_idx[B * T_OUT];

// ---------------------------------------------------------------------------
// Kernel A: per-batch cumsum + searchsorted -> g_idx
// grid = B, block = 1024 (== T)
// ---------------------------------------------------------------------------
__global__ __launch_bounds__(1024) void build_idx_kernel(
    const int* __restrict__ durations,   // [B, T]
    const int* __restrict__ target_len)  // [B]
{
    __shared__ int s_ends[T + 1];        // +1 sentinel so mid==T is a safe read
    __shared__ int s_warp[32];

    const int b   = blockIdx.x;
    const int tid = threadIdx.x;
    const int lane = tid & 31;
    const int wid  = tid >> 5;

    int v = durations[b * T + tid];
    v = v < 0 ? 0 : v;

    // warp inclusive scan
    #pragma unroll
    for (int off = 1; off < 32; off <<= 1) {
        int n = __shfl_up_sync(0xFFFFFFFFu, v, off);
        if (lane >= off) v += n;
    }
    if (lane == 31) s_warp[wid] = v;
    __syncthreads();

    if (wid == 0) {
        int w = s_warp[lane];
        #pragma unroll
        for (int off = 1; off < 32; off <<= 1) {
            int n = __shfl_up_sync(0xFFFFFFFFu, w, off);
            if (lane >= off) w += n;
        }
        s_warp[lane] = w;
    }
    __syncthreads();

    int add = (wid > 0) ? s_warp[wid - 1] : 0;
    s_ends[tid] = v + add;
    if (tid == 0) s_ends[T] = 0x7FFFFFFF;  // sentinel
    __syncthreads();

    const int total = s_ends[T - 1];
    int tl = target_len[b];
    const int limit = total < tl ? total : tl;

    #pragma unroll
    for (int k = 0; k < T_OUT / T; k++) {
        const int pos = tid + k * T;
        // first i with ends[i] > pos; answer space {0..T} -> 11 iterations
        int lo = 0, hi = T;
        #pragma unroll
        for (int it = 0; it < 11; it++) {
            int mid = (lo + hi) >> 1;
            if (s_ends[mid] <= pos) lo = mid + 1; else hi = mid;
        }
        int idx = lo < (T - 1) ? lo : (T - 1);
        g_idx[b * T_OUT + pos] = (pos < limit) ? idx : -1;
    }
}

// ---------------------------------------------------------------------------
// Kernel B: gather rows of x (or zeros) into out, float4-vectorized, ILP=8.
// Each block of 384 threads handles 32 rows; each thread copies one float4
// from each of 8 rows (independent chains -> high MLP).
// grid = B*T_OUT/32 = 4096
// ---------------------------------------------------------------------------
__global__ __launch_bounds__(384) void gather_kernel(
    const float4* __restrict__ x,   // [B, T, 96] as float4
    float4* __restrict__ out)       // [B, T_OUT, 96] as float4
{
    const int tid   = threadIdx.x;
    const int rsub  = tid / F4_PER_ROW;          // 0..3  (row lane)
    const int c     = tid - rsub * F4_PER_ROW;   // 0..95 (column)
    const int base  = blockIdx.x * ROWS_PER_BLOCK;

    int rows[ROWS_PER_THREAD];
    int idxs[ROWS_PER_THREAD];

    // 1) batch all idx loads (independent, one 128B line per block)
    #pragma unroll
    for (int k = 0; k < ROWS_PER_THREAD; k++) {
        rows[k] = base + rsub + k * ROW_LANES;
        idxs[k] = __ldg(&g_idx[rows[k]]);
    }

    // 2) batch all gather loads (independent LDG.128)
    float4 vals[ROWS_PER_THREAD];
    #pragma unroll
    for (int k = 0; k < ROWS_PER_THREAD; k++) {
        const int b   = rows[k] >> 12;           // / T_OUT
        const int idx = idxs[k];
        if (idx >= 0) {
            vals[k] = __ldg(&x[((long)b * T + idx) * F4_PER_ROW + c]);
        } else {
            vals[k] = make_float4(0.f, 0.f, 0.f, 0.f);
        }
    }

    // 3) coalesced stores
    #pragma unroll
    for (int k = 0; k < ROWS_PER_THREAD; k++) {
        out[(long)rows[k] * F4_PER_ROW + c] = vals[k];
    }
}

// ---------------------------------------------------------------------------
extern "C" void kernel_launch(void* const* d_in, const int* in_sizes, int n_in,
                              void* d_out, int out_size)
{
    const float* x          = (const float*)d_in[0];
    const int*   durations  = (const int*)d_in[1];
    const int*   target_len = (const int*)d_in[2];
    float*       out        = (float*)d_out;

    build_idx_kernel<<<B, 1024>>>(durations, target_len);
    gather_kernel<<<(B * T_OUT) / ROWS_PER_BLOCK, 384>>>((const float4*)x, (float4*)out);
}

// round 8
// speedup vs baseline: 1.5797x; 1.1769x over previous
#include <cuda_runtime.h>

#define B 32
#define T 1024
#define D 384
#define T_OUT 4096
#define F4_PER_ROW (D / 4)        // 96
#define ROWS_PER_THREAD 8
#define ROW_LANES 4               // 384 / 96
#define ROWS_PER_BLOCK (ROW_LANES * ROWS_PER_THREAD)   // 32
#define BLOCKS_PER_BATCH (T_OUT / ROWS_PER_BLOCK)      // 128
#define SCAN_THREADS 256          // each scans 4 contiguous durations (int4)

// ---------------------------------------------------------------------------
// Fused kernel: per-block recompute of the batch cumsum (4KB, L2-broadcast),
// searchsorted for this block's 32 rows, then ILP=8 float4 gather.
// grid = B * BLOCKS_PER_BATCH = 4096, block = 384
// ---------------------------------------------------------------------------
__global__ __launch_bounds__(384) void fused_kernel(
    const float4* __restrict__ x,        // [B, T, 96] as float4
    const int4*   __restrict__ dur4,     // [B, T/4] as int4
    const int*    __restrict__ target_len,
    float4*       __restrict__ out)      // [B, T_OUT, 96] as float4
{
    __shared__ int s_ends[T + 1];        // inclusive cumsum + sentinel
    __shared__ int s_warp[SCAN_THREADS / 32];   // 8 warp sums
    __shared__ int s_idx[ROWS_PER_BLOCK];       // idx per row, -1 = zeros

    const int tid   = threadIdx.x;
    const int b     = blockIdx.x / BLOCKS_PER_BATCH;
    const int chunk = blockIdx.x - b * BLOCKS_PER_BATCH;

    // ---- 1) block-local scan of this batch's durations (first 256 threads)
    if (tid < SCAN_THREADS) {
        const int lane = tid & 31;
        const int wid  = tid >> 5;

        int4 d = __ldg(&dur4[b * (T / 4) + tid]);
        int e0 = d.x < 0 ? 0 : d.x;
        int e1 = d.y < 0 ? 0 : d.y;
        int e2 = d.z < 0 ? 0 : d.z;
        int e3 = d.w < 0 ? 0 : d.w;
        // local inclusive prefix over the 4
        int p0 = e0, p1 = p0 + e1, p2 = p1 + e2, p3 = p2 + e3;

        // warp inclusive scan of the per-thread sums (p3)
        int ws = p3;
        #pragma unroll
        for (int off = 1; off < 32; off <<= 1) {
            int n = __shfl_up_sync(0xFFFFFFFFu, ws, off);
            if (lane >= off) ws += n;
        }
        if (lane == 31) s_warp[wid] = ws;
        __syncthreads();

        // scan the 8 warp sums (warp 0, lanes 0..7)
        if (wid == 0 && lane < 8) {
            int w = s_warp[lane];
            #pragma unroll
            for (int off = 1; off < 8; off <<= 1) {
                int n = __shfl_up_sync(0xFFu, w, off);
                if (lane >= off) w += n;
            }
            s_warp[lane] = w;
        }
        __syncthreads();

        const int warp_off = (wid > 0) ? s_warp[wid - 1] : 0;
        const int base = warp_off + (ws - p3);   // exclusive prefix for this thread
        s_ends[4 * tid + 0] = base + p0;
        s_ends[4 * tid + 1] = base + p1;
        s_ends[4 * tid + 2] = base + p2;
        s_ends[4 * tid + 3] = base + p3;
        if (tid == 0) s_ends[T] = 0x7FFFFFFF;    // sentinel
    } else {
        __syncthreads();
        __syncthreads();
    }
    __syncthreads();

    // ---- 2) searchsorted for this block's 32 output positions
    if (tid < ROWS_PER_BLOCK) {
        const int pos   = chunk * ROWS_PER_BLOCK + tid;
        const int total = s_ends[T - 1];
        const int tl    = __ldg(&target_len[b]);
        const int limit = total < tl ? total : tl;

        // first i with ends[i] > pos; answer space {0..T} -> 11 iterations
        int lo = 0, hi = T;
        #pragma unroll
        for (int it = 0; it < 11; it++) {
            int mid = (lo + hi) >> 1;
            if (s_ends[mid] <= pos) lo = mid + 1; else hi = mid;
        }
        int idx = lo < (T - 1) ? lo : (T - 1);
        s_idx[tid] = (pos < limit) ? idx : -1;
    }
    __syncthreads();

    // ---- 3) ILP=8 gather, float4-vectorized, coalesced stores
    const int rsub = tid / F4_PER_ROW;           // 0..3
    const int c    = tid - rsub * F4_PER_ROW;    // 0..95
    const long row_base = (long)b * T_OUT + chunk * ROWS_PER_BLOCK;

    int idxs[ROWS_PER_THREAD];
    #pragma unroll
    for (int k = 0; k < ROWS_PER_THREAD; k++) {
        idxs[k] = s_idx[rsub + k * ROW_LANES];
    }

    float4 vals[ROWS_PER_THREAD];
    #pragma unroll
    for (int k = 0; k < ROWS_PER_THREAD; k++) {
        const int idx = idxs[k];
        if (idx >= 0) {
            vals[k] = __ldg(&x[((long)b * T + idx) * F4_PER_ROW + c]);
        } else {
            vals[k] = make_float4(0.f, 0.f, 0.f, 0.f);
        }
    }

    #pragma unroll
    for (int k = 0; k < ROWS_PER_THREAD; k++) {
        out[(row_base + rsub + k * ROW_LANES) * F4_PER_ROW + c] = vals[k];
    }
}

// ---------------------------------------------------------------------------
extern "C" void kernel_launch(void* const* d_in, const int* in_sizes, int n_in,
                              void* d_out, int out_size)
{
    const float* x          = (const float*)d_in[0];
    const int*   durations  = (const int*)d_in[1];
    const int*   target_len = (const int*)d_in[2];
    float*       out        = (float*)d_out;

    fused_kernel<<<B * BLOCKS_PER_BATCH, 384>>>(
        (const float4*)x, (const int4*)durations, target_len, (float4*)out);
}

// round 11
// speedup vs baseline: 1.6687x; 1.0564x over previous
#include <cuda_runtime.h>

#define B 32
#define T 1024
#define D 384
#define T_OUT 4096
#define F4_PER_ROW (D / 4)        // 96
#define ROWS_PER_THREAD 8
#define ROW_LANES 4               // 384 / 96
#define ROWS_PER_BLOCK (ROW_LANES * ROWS_PER_THREAD)   // 32
#define BLOCKS_PER_BATCH (T_OUT / ROWS_PER_BLOCK)      // 128
#define SCAN_THREADS 256          // each scans 4 contiguous durations (int4)

// ---------------------------------------------------------------------------
// Fused kernel: per-block recompute of the batch cumsum (4KB, L2-broadcast),
// searchsorted for this block's 32 rows, then ILP=8 float4 gather with
// forced front-batched loads and streaming (evict-first) stores.
// grid = B * BLOCKS_PER_BATCH = 4096, block = 384
// ---------------------------------------------------------------------------
__global__ __launch_bounds__(384) void fused_kernel(
    const float4* __restrict__ x,        // [B, T, 96] as float4
    const int4*   __restrict__ dur4,     // [B, T/4] as int4
    const int*    __restrict__ target_len,
    float4*       __restrict__ out)      // [B, T_OUT, 96] as float4
{
    __shared__ int s_ends[T + 1];        // inclusive cumsum + sentinel
    __shared__ int s_warp[SCAN_THREADS / 32];   // 8 warp sums
    __shared__ int s_idx[ROWS_PER_BLOCK];       // idx per row, -1 = zeros

    const int tid   = threadIdx.x;
    const int b     = blockIdx.x / BLOCKS_PER_BATCH;
    const int chunk = blockIdx.x - b * BLOCKS_PER_BATCH;

    // ---- 1) block-local scan of this batch's durations (first 256 threads)
    if (tid < SCAN_THREADS) {
        const int lane = tid & 31;
        const int wid  = tid >> 5;

        int4 d = __ldg(&dur4[b * (T / 4) + tid]);
        int e0 = d.x < 0 ? 0 : d.x;
        int e1 = d.y < 0 ? 0 : d.y;
        int e2 = d.z < 0 ? 0 : d.z;
        int e3 = d.w < 0 ? 0 : d.w;
        // local inclusive prefix over the 4
        int p0 = e0, p1 = p0 + e1, p2 = p1 + e2, p3 = p2 + e3;

        // warp inclusive scan of the per-thread sums (p3)
        int ws = p3;
        #pragma unroll
        for (int off = 1; off < 32; off <<= 1) {
            int n = __shfl_up_sync(0xFFFFFFFFu, ws, off);
            if (lane >= off) ws += n;
        }
        if (lane == 31) s_warp[wid] = ws;
        __syncthreads();

        // scan the 8 warp sums (warp 0, lanes 0..7)
        if (wid == 0 && lane < 8) {
            int w = s_warp[lane];
            #pragma unroll
            for (int off = 1; off < 8; off <<= 1) {
                int n = __shfl_up_sync(0xFFu, w, off);
                if (lane >= off) w += n;
            }
            s_warp[lane] = w;
        }
        __syncthreads();

        const int warp_off = (wid > 0) ? s_warp[wid - 1] : 0;
        const int base = warp_off + (ws - p3);   // exclusive prefix for this thread
        s_ends[4 * tid + 0] = base + p0;
        s_ends[4 * tid + 1] = base + p1;
        s_ends[4 * tid + 2] = base + p2;
        s_ends[4 * tid + 3] = base + p3;
        if (tid == 0) s_ends[T] = 0x7FFFFFFF;    // sentinel
    } else {
        __syncthreads();
        __syncthreads();
    }
    __syncthreads();

    // ---- 2) searchsorted for this block's 32 output positions
    if (tid < ROWS_PER_BLOCK) {
        const int pos   = chunk * ROWS_PER_BLOCK + tid;
        const int total = s_ends[T - 1];
        const int tl    = __ldg(&target_len[b]);
        const int limit = total < tl ? total : tl;

        // first i with ends[i] > pos; answer space {0..T} -> 11 iterations
        int lo = 0, hi = T;
        #pragma unroll
        for (int it = 0; it < 11; it++) {
            int mid = (lo + hi) >> 1;
            if (s_ends[mid] <= pos) lo = mid + 1; else hi = mid;
        }
        int idx = lo < (T - 1) ? lo : (T - 1);
        s_idx[tid] = (pos < limit) ? idx : -1;
    }
    __syncthreads();

    // ---- 3) ILP=8 gather, float4-vectorized, coalesced streaming stores
    const int rsub = tid / F4_PER_ROW;           // 0..3
    const int c    = tid - rsub * F4_PER_ROW;    // 0..95
    const long row_base = (long)b * T_OUT + chunk * ROWS_PER_BLOCK;

    int idxs[ROWS_PER_THREAD];
    #pragma unroll
    for (int k = 0; k < ROWS_PER_THREAD; k++) {
        idxs[k] = s_idx[rsub + k * ROW_LANES];
    }

    float4 vals[ROWS_PER_THREAD];
    #pragma unroll
    for (int k = 0; k < ROWS_PER_THREAD; k++) {
        const int idx = idxs[k];
        if (idx >= 0) {
            vals[k] = __ldg(&x[((long)b * T + idx) * F4_PER_ROW + c]);
        } else {
            vals[k] = make_float4(0.f, 0.f, 0.f, 0.f);
        }
    }

    // Force all 8 loads to be issued (and vals held live) before any store:
    // prevents ptxas from software-pipelining ld/st pairs at low reg count,
    // which collapses MLP to ~2.
    asm volatile("" ::: "memory");

    #pragma unroll
    for (int k = 0; k < ROWS_PER_THREAD; k++) {
        // streaming store: output is never re-read; keep L2 for x reuse
        __stcs(&out[(row_base + rsub + k * ROW_LANES) * F4_PER_ROW + c], vals[k]);
    }
}

// ---------------------------------------------------------------------------
extern "C" void kernel_launch(void* const* d_in, const int* in_sizes, int n_in,
                              void* d_out, int out_size)
{
    const float* x          = (const float*)d_in[0];
    const int*   durations  = (const int*)d_in[1];
    const int*   target_len = (const int*)d_in[2];
    float*       out        = (float*)d_out;

    fused_kernel<<<B * BLOCKS_PER_BATCH, 384>>>(
        (const float4*)x, (const int4*)durations, target_len, (float4*)out);
}